// round 13
// baseline (speedup 1.0000x reference)
#include <cuda_runtime.h>

// NLSearch via column factorization + f32x2-packed FMA.
// colP[x][dy][dx] = sum_{c,i} v0[c][refl(qh-3+i)][refl(x)] *
//                            v1[c][refl(qh-3+i+dy)][refl(x+dx)]
// dists[m][s0,s1] = sum_{j=0..6} colP[4m+j][s0-4][s1-4]
// CTA = (t, n, quarter): 16 queries, NX=67 columns. 160 threads:
// thread (xi = tid>>1 in [0,67), dh = tid&1) owns colP[x0+xi][4dh-4..4dh-1][*]
// as 16 packed f32x2 accumulators. v1 staged as PAIRS so every b-load is an
// aligned LDS.64 and every FMA is fma.rn.f32x2 (no packing movs on b).
// Output float32: [0,86016) dists (1,1,12288,7); [86016,344064) inds (..,7,3).

typedef unsigned long long u64;

#define THREADS 160
#define NX      67
#define RS0     67          // v0s row stride (floats)
#define CS0     469         // v0s channel stride = 7*67
#define PR      74          // v1 pair-row stride (float2 units)
#define PCS     1036        // v1 channel stride = 14*74 (float2 units)
#define V1P_OFF 1876        // float offset of v1 pair array (8B aligned: 7504B)
#define COLP_S  65
#define DISTS_OFF 4480

__device__ __forceinline__ int refl(int x) {
    x = x < 0 ? -x : x;
    return x > 255 ? 510 - x : x;
}
__device__ __forceinline__ u64 pack2(float lo, float hi) {
    u64 d; asm("mov.b64 %0, {%1, %2};" : "=l"(d) : "f"(lo), "f"(hi)); return d;
}
__device__ __forceinline__ u64 fma2(u64 a, u64 b, u64 c) {
    u64 d; asm("fma.rn.f32x2 %0, %1, %2, %3;" : "=l"(d) : "l"(a), "l"(b), "l"(c)); return d;
}
__device__ __forceinline__ void unpack2(u64 v, float& lo, float& hi) {
    asm("mov.b64 {%0, %1}, %2;" : "=f"(lo), "=f"(hi) : "l"(v));
}

__global__ void __launch_bounds__(THREADS, 5)
nls_kernel(const float* __restrict__ vid0,
           const float* __restrict__ vid1,
           float* __restrict__ out)
{
    // phase A: v0s [0,1876) + v1p [1876, 1876+8288) floats
    // phase B: colP [0, 4355) + dists [4480, 5504)
    __shared__ __align__(16) float buf[1876 + 8288];

    const int bx = blockIdx.x;           // 0..767
    const int t  = bx >> 8;
    const int rm = bx & 255;
    const int n  = rm >> 2;
    const int qt = rm & 3;               // column quarter
    const int x0 = (qt << 6) - 3;        // global col of local col 0
    const int qh = n << 2;

    const int tid = threadIdx.x;
    const int xi  = tid >> 1;
    const int dh  = tid & 1;             // dy half: rows start at 4*dh
    const bool act = (tid < 134);

    const float* v0g = vid0 + (size_t)t * 32 * 65536;
    const float* v1g = vid1 + (size_t)t * 32 * 65536;
    float* v1p = buf + V1P_OFF;

    u64 acc[4][4];
#pragma unroll
    for (int q = 0; q < 4; q++)
#pragma unroll
        for (int m = 0; m < 4; m++) acc[q][m] = 0ull;

    for (int c0 = 0; c0 < 32; c0 += 4) {
        __syncthreads();   // previous chunk fully consumed
        // ---- stage chunk: v0 (469 pos) + v1 pairs (14 rows x 75 cols) ----
        for (int pos = tid; pos < 469 + 14 * 75; pos += THREADS) {
            if (pos < 469) {
                int i   = pos / 67;
                int col = pos - i * 67;
                int hg  = refl(qh - 3 + i);
                int wg  = refl(x0 + col);
                const float* s = v0g + ((size_t)c0 << 16) + (hg << 8) + wg;
#pragma unroll
                for (int c = 0; c < 4; c++)
                    buf[c * CS0 + pos] = s[c << 16];
            } else {
                int p2 = pos - 469;
                int r  = p2 / 75;
                int e  = p2 - r * 75;       // window col 0..74
                int hg = refl(qh - 7 + r);
                int wg = refl(x0 - 4 + e);
                const float* s = v1g + ((size_t)c0 << 16) + (hg << 8) + wg;
#pragma unroll
                for (int c = 0; c < 4; c++) {
                    float vv = s[c << 16];
                    int bi = (c * PCS + r * PR) * 2;   // float index of pair row
                    if (e > 0)  v1p[bi + 2 * (e - 1) + 1] = vv;  // .y of pair e-1
                    if (e < 74) v1p[bi + 2 * e]           = vv;  // .x of pair e
                }
            }
        }
        __syncthreads();

        // ---- compute: acc[q][m] += A2[i] *2 B[rr][m], i = rr - q ----
        if (act) {
#pragma unroll
            for (int c = 0; c < 4; c++) {
                const float* va = buf + c * CS0 + xi;
                const float* vb = v1p + (c * PCS + dh * 4 * PR + xi) * 2;
                u64 A2[7];
#pragma unroll
                for (int i = 0; i < 7; i++) {
                    float av = va[i * RS0];
                    A2[i] = pack2(av, av);
                }
#pragma unroll
                for (int rr = 0; rr < 10; rr++) {
                    u64 B[4];
#pragma unroll
                    for (int m = 0; m < 4; m++)
                        B[m] = *(const u64*)(vb + (rr * PR + 2 * m) * 2);
#pragma unroll
                    for (int q = 0; q < 4; q++) {
                        int i = rr - q;
                        if (i >= 0 && i <= 6) {
#pragma unroll
                            for (int m = 0; m < 4; m++)
                                acc[q][m] = fma2(A2[i], B[m], acc[q][m]);
                        }
                    }
                }
            }
        }
    }
    __syncthreads();

    // ---- flush colP[x][s], s = (4dh+q)*8 + 2m (+1) ----
    float* colP  = buf;
    float* dists = buf + DISTS_OFF;
    if (act) {
#pragma unroll
        for (int q = 0; q < 4; q++)
#pragma unroll
            for (int m = 0; m < 4; m++) {
                float lo, hi;
                unpack2(acc[q][m], lo, hi);
                int s = (4 * dh + q) * 8 + 2 * m;
                colP[xi * COLP_S + s]     = lo;
                colP[xi * COLP_S + s + 1] = hi;
            }
    }
    __syncthreads();

    // ---- stage 2: dists[m][s] = sum_{j=0..6} colP[4m+j][s] ----
    for (int idx = tid; idx < 16 * 64; idx += THREADS) {
        int m = idx >> 6;
        int s = idx & 63;
        const float* cp = colP + (4 * m) * COLP_S + s;
        float d = cp[0];
#pragma unroll
        for (int j = 1; j < 7; j++) d += cp[j * COLP_S];
        dists[idx] = d;
    }
    __syncthreads();

    // ---- top-7: warps 0..4, queries m = w, w+5, w+10, (w+15) ----
    const int w    = tid >> 5;
    const int lane = tid & 31;
    for (int m = w; m < 16; m += 5) {
        const float* sd = dists + m * 64;
        float a0 = sd[lane];
        float a1 = sd[lane + 32];
        if (lane == 4) a1 += 1e30f;   // self shift idx 36 boosted for selection

        const int qm = qt * 16 + m;
        const int qg = t * 4096 + n * 64 + qm;
        const int qw = qm << 2;
        float* dbase = out + (size_t)qg * 7;
        float* ibase = out + 86016 + (size_t)qg * 21;

#pragma unroll
        for (int k = 0; k < 7; k++) {
            float bv = (a0 >= a1) ? a0 : a1;
            int   bi = (a0 >= a1) ? lane : lane + 32;
#pragma unroll
            for (int o = 16; o > 0; o >>= 1) {
                float ov = __shfl_xor_sync(0xffffffffu, bv, o);
                int   oi = __shfl_xor_sync(0xffffffffu, bi, o);
                if (ov > bv || (ov == bv && oi < bi)) { bv = ov; bi = oi; }
            }
            if (bi == lane)      a0 = -3.4e38f;
            if (bi == lane + 32) a1 = -3.4e38f;
            if (lane == 0) {
                dbase[k] = sd[bi];
                int s0 = bi >> 3;
                int s1 = bi & 7;
                ibase[k * 3 + 0] = (float)t;
                ibase[k * 3 + 1] = (float)refl(qh + s0 - 4);
                ibase[k * 3 + 2] = (float)refl(qw + s1 - 4);
            }
        }
    }
}

extern "C" void kernel_launch(void* const* d_in, const int* in_sizes, int n_in,
                              void* d_out, int out_size)
{
    const float* vid0 = (const float*)d_in[0];
    const float* vid1 = (const float*)d_in[1];
    float* out = (float*)d_out;
    nls_kernel<<<768, THREADS>>>(vid0, vid1, out);
}

// round 14
// speedup vs baseline: 1.6953x; 1.6953x over previous
#include <cuda_runtime.h>

// NLSearch via column factorization (R12 algorithm, quarter-row CTAs).
// colP[x][dy][dx] = sum_{c,i} v0[c][refl(qh-3+i)][refl(x)] *
//                            v1[c][refl(qh-3+i+dy)][refl(x+dx)]
// dists[m][s0,s1] = sum_{j=0..6} colP[4m+j][s0-4][s1-4]
// CTA = (t, n, quarter qt): 16 queries, NX=67 columns. 160 threads:
// thread (xi = tid>>1 in [0,67), dh = tid&1) owns colP[x0+xi][4dh-4..4dh-1][*]
// as 32 scalar accumulators. Channels streamed in chunks of 4 through smem.
// Output float32: [0,86016) dists (1,1,12288,7); [86016,344064) inds (..,7,3).

#define THREADS 160
#define NX      67
#define RS0     67           // v0s row stride
#define CS0     469          // v0s channel stride = 7*67
#define V1_W    74           // staged v1 cols (xi + s1 up to 66+7)
#define V1_RS   76           // padded row stride: 4*76 = 304 = 16 mod 32 -> dh halves disjoint
#define V1_CS   1064         // 14*76
#define V1_OFF  1876         // float offset of v1s (after 4*469 v0s)
#define COLP_S  65
#define DISTS_OFF 4416

__device__ __forceinline__ int refl(int x) {
    x = x < 0 ? -x : x;
    return x > 255 ? 510 - x : x;
}

__global__ void __launch_bounds__(THREADS, 6)
nls_kernel(const float* __restrict__ vid0,
           const float* __restrict__ vid1,
           float* __restrict__ out)
{
    // phase A: v0s [0,1876) + v1s [1876, 1876+4256)
    // phase B: colP [0, 4355) + dists [4416, 5440)
    __shared__ float buf[1876 + 4256];
    float* v1s = buf + V1_OFF;

    const int bx = blockIdx.x;           // 0..767
    const int t  = bx >> 8;
    const int rm = bx & 255;
    const int n  = rm >> 2;
    const int qt = rm & 3;               // column quarter
    const int x0 = (qt << 6) - 3;        // global col of local col 0
    const int qh = n << 2;

    const int tid = threadIdx.x;
    const int xi  = tid >> 1;
    const int dh  = tid & 1;             // dy half: b rows start at 4*dh
    const bool act = (tid < 134);        // 67*2 items

    const float* v0g = vid0 + (size_t)t * 32 * 65536;
    const float* v1g = vid1 + (size_t)t * 32 * 65536;

    float acc[4][8];
#pragma unroll
    for (int q = 0; q < 4; q++)
#pragma unroll
        for (int s1 = 0; s1 < 8; s1++) acc[q][s1] = 0.f;

    for (int c0 = 0; c0 < 32; c0 += 4) {
        __syncthreads();   // previous chunk fully consumed
        // ---- stage chunk: v0 (469 pos) + v1 (14 x 74 pos) ----
        for (int pos = tid; pos < 469 + 14 * V1_W; pos += THREADS) {
            if (pos < 469) {
                int i   = pos / 67;
                int col = pos - i * 67;
                int hg  = refl(qh - 3 + i);
                int wg  = refl(x0 + col);
                const float* s = v0g + ((size_t)c0 << 16) + (hg << 8) + wg;
#pragma unroll
                for (int c = 0; c < 4; c++)
                    buf[c * CS0 + pos] = s[c << 16];
            } else {
                int p2 = pos - 469;
                int r  = p2 / V1_W;
                int e  = p2 - r * V1_W;
                int hg = refl(qh - 7 + r);
                int wg = refl(x0 - 4 + e);
                const float* s = v1g + ((size_t)c0 << 16) + (hg << 8) + wg;
#pragma unroll
                for (int c = 0; c < 4; c++)
                    v1s[c * V1_CS + r * V1_RS + e] = s[c << 16];
            }
        }
        __syncthreads();

        // ---- compute: acc[q][s1] += a[i] * b[rr][s1], i = rr - q ----
        if (act) {
#pragma unroll
            for (int c = 0; c < 4; c++) {
                const float* va = buf + c * CS0 + xi;
                const float* vb = v1s + c * V1_CS + dh * (4 * V1_RS) + xi;
                float a[7];
#pragma unroll
                for (int i = 0; i < 7; i++) a[i] = va[i * RS0];
#pragma unroll
                for (int rr = 0; rr < 10; rr++) {
                    float bv[8];
#pragma unroll
                    for (int s1 = 0; s1 < 8; s1++) bv[s1] = vb[rr * V1_RS + s1];
#pragma unroll
                    for (int q = 0; q < 4; q++) {
                        int i = rr - q;
                        if (i >= 0 && i <= 6) {
#pragma unroll
                            for (int s1 = 0; s1 < 8; s1++)
                                acc[q][s1] = fmaf(a[i], bv[s1], acc[q][s1]);
                        }
                    }
                }
            }
        }
    }
    __syncthreads();

    // ---- flush colP: s = (4*dh+q)*8 + s1 ----
    float* colP  = buf;
    float* dists = buf + DISTS_OFF;
    if (act) {
#pragma unroll
        for (int q = 0; q < 4; q++)
#pragma unroll
            for (int s1 = 0; s1 < 8; s1++)
                colP[xi * COLP_S + (4 * dh + q) * 8 + s1] = acc[q][s1];
    }
    __syncthreads();

    // ---- stage 2: dists[m][s] = sum_{j=0..6} colP[4m+j][s] ----
    for (int idx = tid; idx < 16 * 64; idx += THREADS) {
        int m = idx >> 6;
        int s = idx & 63;
        const float* cp = colP + (4 * m) * COLP_S + s;
        float d = cp[0];
#pragma unroll
        for (int j = 1; j < 7; j++) d += cp[j * COLP_S];
        dists[idx] = d;
    }
    __syncthreads();

    // ---- top-7: warps 0..4 take queries m = w, w+5, w+10, w+15 ----
    const int w    = tid >> 5;
    const int lane = tid & 31;
    for (int m = w; m < 16; m += 5) {
        const float* sd = dists + m * 64;
        float a0 = sd[lane];
        float a1 = sd[lane + 32];
        if (lane == 4) a1 += 1e30f;   // self shift idx 36 boosted for selection

        const int qm = qt * 16 + m;
        const int qg = t * 4096 + n * 64 + qm;
        const int qw = qm << 2;
        float* dbase = out + (size_t)qg * 7;
        float* ibase = out + 86016 + (size_t)qg * 21;

#pragma unroll
        for (int k = 0; k < 7; k++) {
            float bv = (a0 >= a1) ? a0 : a1;
            int   bi = (a0 >= a1) ? lane : lane + 32;
#pragma unroll
            for (int o = 16; o > 0; o >>= 1) {
                float ov = __shfl_xor_sync(0xffffffffu, bv, o);
                int   oi = __shfl_xor_sync(0xffffffffu, bi, o);
                if (ov > bv || (ov == bv && oi < bi)) { bv = ov; bi = oi; }
            }
            if (bi == lane)      a0 = -3.4e38f;
            if (bi == lane + 32) a1 = -3.4e38f;
            if (lane == 0) {
                dbase[k] = sd[bi];
                int s0 = bi >> 3;
                int s1 = bi & 7;
                ibase[k * 3 + 0] = (float)t;
                ibase[k * 3 + 1] = (float)refl(qh + s0 - 4);
                ibase[k * 3 + 2] = (float)refl(qw + s1 - 4);
            }
        }
    }
}

extern "C" void kernel_launch(void* const* d_in, const int* in_sizes, int n_in,
                              void* d_out, int out_size)
{
    const float* vid0 = (const float*)d_in[0];
    const float* vid1 = (const float*)d_in[1];
    float* out = (float*)d_out;
    nls_kernel<<<768, THREADS>>>(vid0, vid1, out);
}

// round 15
// speedup vs baseline: 1.6959x; 1.0004x over previous
#include <cuda_runtime.h>
#include <cstdint>

// NLSearch via column factorization (R12 geometry) + cp.async double buffering.
// colP[x][dy][dx] = sum_{c,i} v0[c][refl(qh-3+i)][refl(x)] *
//                            v1[c][refl(qh-3+i+dy)][refl(x+dx)]
// dists[m][s0,s1] = sum_{j=0..6} colP[4m+j][s0-4][s1-4]
// CTA = (t, n, half-row h0): 32 queries, NX=131 columns, 288 threads.
// Thread (xi = tid>>1 in [0,131), dh = tid&1) owns colP[x0+xi][4dh-4..4dh-1][*].
// Channels streamed in chunks of 2 via cp.async into a double buffer; staging
// offsets (reflect + address math) precomputed once into a smem table.
// Output float32: [0,86016) dists (1,1,12288,7); [86016,344064) inds (..,7,3).

#define THREADS 288
#define NPOS    2849          // 917 v0 positions + 14*138 v1 positions
#define RS0     131           // v0 row stride
#define CS0     917           // v0 per-channel size (7*131)
#define V1W     138           // staged v1 cols
#define V1RS    140           // padded v1 row stride (4*140 = 16 mod 32 -> dh halves disjoint)
#define CS1     1960          // v1 per-channel size (14*140)
#define V1BASE  1834          // float offset of v1 within a buffer (2*917)
#define BUF     5754          // floats per buffer (2*917 + 2*1960)
#define OFFT_F  11508         // float index where the u32 offset table starts
#define COLP_S  65
#define DISTS_F 8515
#define SMEM_BYTES (11508*4 + 2849*4)

__device__ __forceinline__ int refl(int x) {
    x = x < 0 ? -x : x;
    return x > 255 ? 510 - x : x;
}
__device__ __forceinline__ void cp_async4(uint32_t saddr, const float* gaddr) {
    asm volatile("cp.async.ca.shared.global [%0], [%1], 4;" :: "r"(saddr), "l"(gaddr));
}

__global__ void __launch_bounds__(THREADS, 3)
nls_kernel(const float* __restrict__ vid0,
           const float* __restrict__ vid1,
           float* __restrict__ out)
{
    extern __shared__ float smem[];
    uint32_t* offt = (uint32_t*)(smem + OFFT_F);
    uint32_t sbase;
    asm("{ .reg .u64 t; cvta.to.shared.u64 t, %1; cvt.u32.u64 %0, t; }"
        : "=r"(sbase) : "l"(smem));

    const int bx  = blockIdx.x;          // 0..383
    const int t   = bx >> 7;
    const int rem = bx & 127;
    const int n   = rem >> 1;
    const int h0  = rem & 1;
    const int x0  = 128 * h0 - 3;
    const int qh  = n << 2;

    const int tid = threadIdx.x;
    const int xi  = tid >> 1;
    const int dh  = tid & 1;
    const bool act = (tid < 262);

    const float* v0g = vid0 + (size_t)t * 32 * 65536;
    const float* v1g = vid1 + (size_t)t * 32 * 65536;

    // ---- precompute staging offsets once: (gidx<<16) | sidx ----
    for (int pos = tid; pos < NPOS; pos += THREADS) {
        int gidx, sidx;
        if (pos < CS0) {
            int i   = pos / 131;
            int col = pos - i * 131;
            gidx = (refl(qh - 3 + i) << 8) + refl(x0 + col);
            sidx = pos;
        } else {
            int p2 = pos - CS0;
            int r  = p2 / V1W;
            int e  = p2 - r * V1W;
            gidx = (refl(qh - 7 + r) << 8) + refl(x0 - 4 + e);
            sidx = V1BASE + r * V1RS + e;
        }
        offt[pos] = ((uint32_t)gidx << 16) | (uint32_t)sidx;
    }
    __syncthreads();

    float acc[4][8];
#pragma unroll
    for (int q = 0; q < 4; q++)
#pragma unroll
        for (int s1 = 0; s1 < 8; s1++) acc[q][s1] = 0.f;

    // ---- stage chunk (2 channels c0, c0+1) into buffer at float base fb ----
    auto stage = [&](int c0, int fb) {
#pragma unroll
        for (int it = 0; it < 10; it++) {
            int pos = tid + it * THREADS;
            if (pos < NPOS) {
                uint32_t o = offt[pos];
                uint32_t sidx = o & 0xffffu;
                uint32_t gidx = o >> 16;
                bool isv0 = sidx < (uint32_t)CS0;
                const float* g = (isv0 ? v0g : v1g) + ((size_t)c0 << 16) + gidx;
                uint32_t cs = isv0 ? CS0 : CS1;
                uint32_t sa = sbase + (uint32_t)(fb + sidx) * 4u;
                cp_async4(sa, g);
                cp_async4(sa + cs * 4u, g + 65536);
            }
        }
        asm volatile("cp.async.commit_group;");
    };

    stage(0, 0);

    for (int k = 0; k < 16; k++) {
        const int fb = (k & 1) ? BUF : 0;
        asm volatile("cp.async.wait_group 0;" ::: "memory");
        __syncthreads();
        if (k < 15) stage(2 * (k + 1), fb ^ BUF);

        if (act) {
#pragma unroll
            for (int c = 0; c < 2; c++) {
                const float* va = smem + fb + c * CS0 + xi;
                const float* vb = smem + fb + V1BASE + c * CS1 + dh * (4 * V1RS) + xi;
                float a[7];
#pragma unroll
                for (int i = 0; i < 7; i++) a[i] = va[i * RS0];
#pragma unroll
                for (int rr = 0; rr < 10; rr++) {
                    float bv[8];
#pragma unroll
                    for (int s1 = 0; s1 < 8; s1++) bv[s1] = vb[rr * V1RS + s1];
#pragma unroll
                    for (int q = 0; q < 4; q++) {
                        int i = rr - q;
                        if (i >= 0 && i <= 6) {
#pragma unroll
                            for (int s1 = 0; s1 < 8; s1++)
                                acc[q][s1] = fmaf(a[i], bv[s1], acc[q][s1]);
                        }
                    }
                }
            }
        }
    }
    __syncthreads();

    // ---- flush colP: s = (4*dh+q)*8 + s1 ----
    float* colP  = smem;
    float* dists = smem + DISTS_F;
    if (act) {
#pragma unroll
        for (int q = 0; q < 4; q++)
#pragma unroll
            for (int s1 = 0; s1 < 8; s1++)
                colP[xi * COLP_S + (4 * dh + q) * 8 + s1] = acc[q][s1];
    }
    __syncthreads();

    // ---- stage 2: dists[m][s] = sum_{j=0..6} colP[4m+j][s] ----
    for (int idx = tid; idx < 32 * 64; idx += THREADS) {
        int m = idx >> 6;
        int s = idx & 63;
        const float* cp = colP + (4 * m) * COLP_S + s;
        float d = cp[0];
#pragma unroll
        for (int j = 1; j < 7; j++) d += cp[j * COLP_S];
        dists[idx] = d;
    }
    __syncthreads();

    // ---- top-7: warps 0..7 handle 4 queries each ----
    const int w    = tid >> 5;
    const int lane = tid & 31;
    if (w < 8) {
        for (int mi = 0; mi < 4; mi++) {
            int m = w * 4 + mi;
            const float* sd = dists + m * 64;
            float a0 = sd[lane];
            float a1 = sd[lane + 32];
            if (lane == 4) a1 += 1e30f;   // self shift idx 36 boosted

            const int qm = h0 * 32 + m;
            const int qg = t * 4096 + n * 64 + qm;
            const int qw = qm << 2;
            float* dbase = out + (size_t)qg * 7;
            float* ibase = out + 86016 + (size_t)qg * 21;

#pragma unroll
            for (int k = 0; k < 7; k++) {
                float bv = (a0 >= a1) ? a0 : a1;
                int   bi = (a0 >= a1) ? lane : lane + 32;
#pragma unroll
                for (int o = 16; o > 0; o >>= 1) {
                    float ov = __shfl_xor_sync(0xffffffffu, bv, o);
                    int   oi = __shfl_xor_sync(0xffffffffu, bi, o);
                    if (ov > bv || (ov == bv && oi < bi)) { bv = ov; bi = oi; }
                }
                if (bi == lane)      a0 = -3.4e38f;
                if (bi == lane + 32) a1 = -3.4e38f;
                if (lane == 0) {
                    dbase[k] = sd[bi];
                    int s0 = bi >> 3;
                    int s1 = bi & 7;
                    ibase[k * 3 + 0] = (float)t;
                    ibase[k * 3 + 1] = (float)refl(qh + s0 - 4);
                    ibase[k * 3 + 2] = (float)refl(qw + s1 - 4);
                }
            }
        }
    }
}

extern "C" void kernel_launch(void* const* d_in, const int* in_sizes, int n_in,
                              void* d_out, int out_size)
{
    const float* vid0 = (const float*)d_in[0];
    const float* vid1 = (const float*)d_in[1];
    float* out = (float*)d_out;
    cudaFuncSetAttribute(nls_kernel, cudaFuncAttributeMaxDynamicSharedMemorySize,
                         SMEM_BYTES);
    nls_kernel<<<384, THREADS, SMEM_BYTES>>>(vid0, vid1, out);
}

// round 16
// speedup vs baseline: 1.8594x; 1.0964x over previous
#include <cuda_runtime.h>
#include <cstdint>

// NLSearch via column factorization (R12 geometry) + vectorized staging.
// colP[x][dy][dx] = sum_{c,i} v0[c][refl(qh-3+i)][refl(x)] *
//                            v1[c][refl(qh-3+i+dy)][refl(x+dx)]
// dists[m][s0,s1] = sum_{j=0..6} colP[4m+j][s0-4][s1-4]
// CTA = (t, n, half-row h0): 32 queries, NX=131 cols, 288 threads.
// Thread (xi = tid>>1 in [0,131), dh = tid&1) owns colP[x0+xi][4dh-4..4dh-1][*].
// Channels streamed in chunks of 4; interior staged as LDG.128/STS.128 quads
// (+1-shifted smem rows make both sides 16B-aligned), reflected edges scalar.
// All index math hoisted into a one-time packed offset table.
// Output float32: [0,86016) dists (1,1,12288,7); [86016,344064) inds (..,7,3).

#define THREADS 288
#define RS0     132           // v0 row stride (floats), col stored at +1
#define CS0     924           // 7*132
#define V1BASE  3696          // float offset of v1 section (4*924)
#define RS1     140           // v1 row stride, e stored at +1 (4*140 = 16 mod 32)
#define CS1     1960          // 14*140
#define BUFF    11536         // 3696 + 4*1960
#define NQ0     224           // v0 quads: 7 rows * 32
#define NQ1     448           // v1 quads: 14 rows * 32 (e = 7+4m)
#define NS0     21            // v0 scalars: 7 rows * {0,1,2}
#define NS1     140           // v1 scalars: 14 rows * {0..6,135,136,137}
#define NPOS    (NQ0+NQ1+NS0+NS1)   // 833
#define COLP_S  65
#define DISTS_F 8576
#define SMEM_BYTES ((BUFF + NPOS) * 4)

__device__ __forceinline__ int refl(int x) {
    x = x < 0 ? -x : x;
    return x > 255 ? 510 - x : x;
}

__global__ void __launch_bounds__(THREADS, 3)
nls_kernel(const float* __restrict__ vid0,
           const float* __restrict__ vid1,
           float* __restrict__ out)
{
    extern __shared__ float smem[];
    uint32_t* offt = (uint32_t*)(smem + BUFF);

    const int bx  = blockIdx.x;          // 0..383
    const int t   = bx >> 7;
    const int rem = bx & 127;
    const int n   = rem >> 1;
    const int h0  = rem & 1;
    const int x0  = 128 * h0 - 3;
    const int qh  = n << 2;

    const int tid = threadIdx.x;
    const int xi  = tid >> 1;
    const int dh  = tid & 1;
    const bool act = (tid < 262);

    const float* v0g = vid0 + (size_t)t * 32 * 65536;
    const float* v1g = vid1 + (size_t)t * 32 * 65536;

    // ---- build offset table once: (gidx<<16) | sidx (channel-relative) ----
    for (int p = tid; p < NPOS; p += THREADS) {
        int gidx, sidx;
        if (p < NQ0) {                       // v0 interior quad
            int i = p >> 5, m = p & 31, col = 3 + 4 * m;
            gidx = (refl(qh - 3 + i) << 8) + (x0 + col);       // col in range
            sidx = i * RS0 + col + 1;
        } else if (p < NQ0 + NQ1) {          // v1 interior quad
            int p2 = p - NQ0;
            int r = p2 >> 5, m = p2 & 31, e = 7 + 4 * m;
            gidx = (refl(qh - 7 + r) << 8) + (x0 - 4 + e);     // in range
            sidx = r * RS1 + e + 1;
        } else if (p < NQ0 + NQ1 + NS0) {    // v0 edge scalar
            int ps = p - (NQ0 + NQ1);
            int i = ps / 3, col = ps - 3 * i;
            gidx = (refl(qh - 3 + i) << 8) + refl(x0 + col);
            sidx = i * RS0 + col + 1;
        } else {                             // v1 edge scalar
            int ps = p - (NQ0 + NQ1 + NS0);
            int r = ps / 10, j = ps - 10 * r;
            int e = (j < 7) ? j : j + 128;   // {0..6,135,136,137}
            gidx = (refl(qh - 7 + r) << 8) + refl(x0 - 4 + e);
            sidx = r * RS1 + e + 1;
        }
        offt[p] = ((uint32_t)gidx << 16) | (uint32_t)sidx;
    }

    float acc[4][8];
#pragma unroll
    for (int q = 0; q < 4; q++)
#pragma unroll
        for (int s1 = 0; s1 < 8; s1++) acc[q][s1] = 0.f;

    for (int c0 = 0; c0 < 32; c0 += 4) {
        __syncthreads();   // prev chunk consumed (and table ready on iter 0)

        // ---- stage chunk of 4 channels via table ----
#pragma unroll
        for (int it = 0; it < 3; it++) {
            int p = tid + it * THREADS;
            if (p < NPOS) {
                uint32_t o = offt[p];
                int sidx = o & 0xffffu;
                int gidx = o >> 16;
                bool isv0 = (p < NQ0) || (p >= NQ0 + NQ1 && p < NQ0 + NQ1 + NS0);
                bool isq  = (p < NQ0 + NQ1);
                const float* g = (isv0 ? v0g : v1g) + ((size_t)c0 << 16) + gidx;
                float* s = smem + (isv0 ? 0 : V1BASE) + sidx;
                int scs = isv0 ? CS0 : CS1;
                if (isq) {
#pragma unroll
                    for (int c = 0; c < 4; c++)
                        *(float4*)(s + c * scs) = *(const float4*)(g + (c << 16));
                } else {
#pragma unroll
                    for (int c = 0; c < 4; c++)
                        s[c * scs] = g[c << 16];
                }
            }
        }
        __syncthreads();

        // ---- compute: acc[q][s1] += a[i] * b[rr][s1], i = rr - q ----
        if (act) {
#pragma unroll
            for (int c = 0; c < 4; c++) {
                const float* va = smem + c * CS0 + xi + 1;
                const float* vb = smem + V1BASE + c * CS1 + dh * (4 * RS1) + xi + 1;
                float a[7];
#pragma unroll
                for (int i = 0; i < 7; i++) a[i] = va[i * RS0];
#pragma unroll
                for (int rr = 0; rr < 10; rr++) {
                    float bv[8];
#pragma unroll
                    for (int s1 = 0; s1 < 8; s1++) bv[s1] = vb[rr * RS1 + s1];
#pragma unroll
                    for (int q = 0; q < 4; q++) {
                        int i = rr - q;
                        if (i >= 0 && i <= 6) {
#pragma unroll
                            for (int s1 = 0; s1 < 8; s1++)
                                acc[q][s1] = fmaf(a[i], bv[s1], acc[q][s1]);
                        }
                    }
                }
            }
        }
    }
    __syncthreads();

    // ---- flush colP: s = (4*dh+q)*8 + s1 ----
    float* colP  = smem;
    float* dists = smem + DISTS_F;
    if (act) {
#pragma unroll
        for (int q = 0; q < 4; q++)
#pragma unroll
            for (int s1 = 0; s1 < 8; s1++)
                colP[xi * COLP_S + (4 * dh + q) * 8 + s1] = acc[q][s1];
    }
    __syncthreads();

    // ---- stage 2: dists[m][s] = sum_{j=0..6} colP[4m+j][s] ----
    for (int idx = tid; idx < 32 * 64; idx += THREADS) {
        int m = idx >> 6;
        int s = idx & 63;
        const float* cp = colP + (4 * m) * COLP_S + s;
        float d = cp[0];
#pragma unroll
        for (int j = 1; j < 7; j++) d += cp[j * COLP_S];
        dists[idx] = d;
    }
    __syncthreads();

    // ---- top-7: warps 0..7 handle 4 queries each ----
    const int w    = tid >> 5;
    const int lane = tid & 31;
    if (w < 8) {
        for (int mi = 0; mi < 4; mi++) {
            int m = w * 4 + mi;
            const float* sd = dists + m * 64;
            float a0 = sd[lane];
            float a1 = sd[lane + 32];
            if (lane == 4) a1 += 1e30f;   // self shift idx 36 boosted

            const int qm = h0 * 32 + m;
            const int qg = t * 4096 + n * 64 + qm;
            const int qw = qm << 2;
            float* dbase = out + (size_t)qg * 7;
            float* ibase = out + 86016 + (size_t)qg * 21;

#pragma unroll
            for (int k = 0; k < 7; k++) {
                float bv = (a0 >= a1) ? a0 : a1;
                int   bi = (a0 >= a1) ? lane : lane + 32;
#pragma unroll
                for (int o = 16; o > 0; o >>= 1) {
                    float ov = __shfl_xor_sync(0xffffffffu, bv, o);
                    int   oi = __shfl_xor_sync(0xffffffffu, bi, o);
                    if (ov > bv || (ov == bv && oi < bi)) { bv = ov; bi = oi; }
                }
                if (bi == lane)      a0 = -3.4e38f;
                if (bi == lane + 32) a1 = -3.4e38f;
                if (lane == 0) {
                    dbase[k] = sd[bi];
                    int s0 = bi >> 3;
                    int s1 = bi & 7;
                    ibase[k * 3 + 0] = (float)t;
                    ibase[k * 3 + 1] = (float)refl(qh + s0 - 4);
                    ibase[k * 3 + 2] = (float)refl(qw + s1 - 4);
                }
            }
        }
    }
}

extern "C" void kernel_launch(void* const* d_in, const int* in_sizes, int n_in,
                              void* d_out, int out_size)
{
    const float* vid0 = (const float*)d_in[0];
    const float* vid1 = (const float*)d_in[1];
    float* out = (float*)d_out;
    cudaFuncSetAttribute(nls_kernel, cudaFuncAttributeMaxDynamicSharedMemorySize,
                         SMEM_BYTES);
    nls_kernel<<<384, THREADS, SMEM_BYTES>>>(vid0, vid1, out);
}

// round 17
// speedup vs baseline: 1.9120x; 1.0283x over previous
#include <cuda_runtime.h>
#include <cstdint>

// NLSearch via column factorization (R16 algorithm, 4-way thread split).
// colP[x][dy][dx] = sum_{c,i} v0[c][refl(qh-3+i)][refl(x)] *
//                            v1[c][refl(qh-3+i+dy)][refl(x+dx)]
// dists[m][s0,s1] = sum_{j=0..6} colP[4m+j][s0-4][s1-4]
// CTA = (t, n, half-row h0): 32 queries, NX=131 cols, 576 threads.
// Thread (xi=tid>>2 in [0,131), dh=(tid>>1)&1, dxh=tid&1) owns
// colP[x0+xi][4dh-4..4dh-1][4dxh..4dxh+3] -> 16 register accumulators.
// Channels in chunks of 4; interior staged as LDG.128/STS.128 quads,
// reflected edges scalar; index math hoisted into a one-time offset table.
// Output float32: [0,86016) dists (1,1,12288,7); [86016,344064) inds (..,7,3).

#define THREADS 576
#define RS0     132           // v0 row stride (floats), col stored at +1
#define CS0     924           // 7*132
#define V1BASE  3696          // float offset of v1 section (4*924)
#define RS1     140           // v1 row stride, e stored at +1 (4*140 = 16 mod 32)
#define CS1     1960          // 14*140
#define BUFF    11536         // 3696 + 4*1960
#define NQ0     224           // v0 quads: 7 rows * 32
#define NQ1     448           // v1 quads: 14 rows * 32 (e = 7+4m)
#define NS0     21            // v0 scalars: 7 rows * {0,1,2}
#define NS1     140           // v1 scalars: 14 rows * {0..6,135,136,137}
#define NPOS    (NQ0+NQ1+NS0+NS1)   // 833
#define COLP_S  65
#define DISTS_F 8576
#define SMEM_BYTES ((BUFF + NPOS) * 4)

__device__ __forceinline__ int refl(int x) {
    x = x < 0 ? -x : x;
    return x > 255 ? 510 - x : x;
}

__global__ void __launch_bounds__(THREADS, 2)
nls_kernel(const float* __restrict__ vid0,
           const float* __restrict__ vid1,
           float* __restrict__ out)
{
    extern __shared__ float smem[];
    uint32_t* offt = (uint32_t*)(smem + BUFF);

    const int bx  = blockIdx.x;          // 0..383
    const int t   = bx >> 7;
    const int rem = bx & 127;
    const int n   = rem >> 1;
    const int h0  = rem & 1;
    const int x0  = 128 * h0 - 3;
    const int qh  = n << 2;

    const int tid = threadIdx.x;
    const int xi  = tid >> 2;            // 0..143, active < 131
    const int dh  = (tid >> 1) & 1;      // dy half
    const int dxh = tid & 1;             // dx half
    const bool act = (xi < 131);

    const float* v0g = vid0 + (size_t)t * 32 * 65536;
    const float* v1g = vid1 + (size_t)t * 32 * 65536;

    // ---- build offset table once: (gidx<<16) | sidx (channel-relative) ----
    for (int p = tid; p < NPOS; p += THREADS) {
        int gidx, sidx;
        if (p < NQ0) {                       // v0 interior quad
            int i = p >> 5, m = p & 31, col = 3 + 4 * m;
            gidx = (refl(qh - 3 + i) << 8) + (x0 + col);
            sidx = i * RS0 + col + 1;
        } else if (p < NQ0 + NQ1) {          // v1 interior quad
            int p2 = p - NQ0;
            int r = p2 >> 5, m = p2 & 31, e = 7 + 4 * m;
            gidx = (refl(qh - 7 + r) << 8) + (x0 - 4 + e);
            sidx = r * RS1 + e + 1;
        } else if (p < NQ0 + NQ1 + NS0) {    // v0 edge scalar
            int ps = p - (NQ0 + NQ1);
            int i = ps / 3, col = ps - 3 * i;
            gidx = (refl(qh - 3 + i) << 8) + refl(x0 + col);
            sidx = i * RS0 + col + 1;
        } else {                             // v1 edge scalar
            int ps = p - (NQ0 + NQ1 + NS0);
            int r = ps / 10, j = ps - 10 * r;
            int e = (j < 7) ? j : j + 128;
            gidx = (refl(qh - 7 + r) << 8) + refl(x0 - 4 + e);
            sidx = r * RS1 + e + 1;
        }
        offt[p] = ((uint32_t)gidx << 16) | (uint32_t)sidx;
    }

    float acc[4][4];
#pragma unroll
    for (int q = 0; q < 4; q++)
#pragma unroll
        for (int jj = 0; jj < 4; jj++) acc[q][jj] = 0.f;

    for (int c0 = 0; c0 < 32; c0 += 4) {
        __syncthreads();   // prev chunk consumed (and table ready on iter 0)

        // ---- stage chunk of 4 channels via table ----
#pragma unroll
        for (int it = 0; it < 2; it++) {
            int p = tid + it * THREADS;
            if (p < NPOS) {
                uint32_t o = offt[p];
                int sidx = o & 0xffffu;
                int gidx = o >> 16;
                bool isv0 = (p < NQ0) || (p >= NQ0 + NQ1 && p < NQ0 + NQ1 + NS0);
                bool isq  = (p < NQ0 + NQ1);
                const float* g = (isv0 ? v0g : v1g) + ((size_t)c0 << 16) + gidx;
                float* s = smem + (isv0 ? 0 : V1BASE) + sidx;
                int scs = isv0 ? CS0 : CS1;
                if (isq) {
#pragma unroll
                    for (int c = 0; c < 4; c++)
                        *(float4*)(s + c * scs) = *(const float4*)(g + (c << 16));
                } else {
#pragma unroll
                    for (int c = 0; c < 4; c++)
                        s[c * scs] = g[c << 16];
                }
            }
        }
        __syncthreads();

        // ---- compute: acc[q][jj] += a[i] * b[rr][4dxh+jj], i = rr - q ----
        if (act) {
#pragma unroll
            for (int c = 0; c < 4; c++) {
                const float* va = smem + c * CS0 + xi + 1;
                const float* vb = smem + V1BASE + c * CS1 + dh * (4 * RS1)
                                  + xi + 1 + 4 * dxh;
                float a[7];
#pragma unroll
                for (int i = 0; i < 7; i++) a[i] = va[i * RS0];
#pragma unroll
                for (int rr = 0; rr < 10; rr++) {
                    float bv[4];
#pragma unroll
                    for (int jj = 0; jj < 4; jj++) bv[jj] = vb[rr * RS1 + jj];
#pragma unroll
                    for (int q = 0; q < 4; q++) {
                        int i = rr - q;
                        if (i >= 0 && i <= 6) {
#pragma unroll
                            for (int jj = 0; jj < 4; jj++)
                                acc[q][jj] = fmaf(a[i], bv[jj], acc[q][jj]);
                        }
                    }
                }
            }
        }
    }
    __syncthreads();

    // ---- flush colP: s = (4*dh+q)*8 + 4*dxh + jj ----
    float* colP  = smem;
    float* dists = smem + DISTS_F;
    if (act) {
#pragma unroll
        for (int q = 0; q < 4; q++)
#pragma unroll
            for (int jj = 0; jj < 4; jj++)
                colP[xi * COLP_S + (4 * dh + q) * 8 + 4 * dxh + jj] = acc[q][jj];
    }
    __syncthreads();

    // ---- stage 2: dists[m][s] = sum_{j=0..6} colP[4m+j][s] ----
    for (int idx = tid; idx < 32 * 64; idx += THREADS) {
        int m = idx >> 6;
        int s = idx & 63;
        const float* cp = colP + (4 * m) * COLP_S + s;
        float d = cp[0];
#pragma unroll
        for (int j = 1; j < 7; j++) d += cp[j * COLP_S];
        dists[idx] = d;
    }
    __syncthreads();

    // ---- top-7: warps 0..7 handle 4 queries each ----
    const int w    = tid >> 5;
    const int lane = tid & 31;
    if (w < 8) {
        for (int mi = 0; mi < 4; mi++) {
            int m = w * 4 + mi;
            const float* sd = dists + m * 64;
            float a0 = sd[lane];
            float a1 = sd[lane + 32];
            if (lane == 4) a1 += 1e30f;   // self shift idx 36 boosted

            const int qm = h0 * 32 + m;
            const int qg = t * 4096 + n * 64 + qm;
            const int qw = qm << 2;
            float* dbase = out + (size_t)qg * 7;
            float* ibase = out + 86016 + (size_t)qg * 21;

#pragma unroll
            for (int k = 0; k < 7; k++) {
                float bv = (a0 >= a1) ? a0 : a1;
                int   bi = (a0 >= a1) ? lane : lane + 32;
#pragma unroll
                for (int o = 16; o > 0; o >>= 1) {
                    float ov = __shfl_xor_sync(0xffffffffu, bv, o);
                    int   oi = __shfl_xor_sync(0xffffffffu, bi, o);
                    if (ov > bv || (ov == bv && oi < bi)) { bv = ov; bi = oi; }
                }
                if (bi == lane)      a0 = -3.4e38f;
                if (bi == lane + 32) a1 = -3.4e38f;
                if (lane == 0) {
                    dbase[k] = sd[bi];
                    int s0 = bi >> 3;
                    int s1 = bi & 7;
                    ibase[k * 3 + 0] = (float)t;
                    ibase[k * 3 + 1] = (float)refl(qh + s0 - 4);
                    ibase[k * 3 + 2] = (float)refl(qw + s1 - 4);
                }
            }
        }
    }
}

extern "C" void kernel_launch(void* const* d_in, const int* in_sizes, int n_in,
                              void* d_out, int out_size)
{
    const float* vid0 = (const float*)d_in[0];
    const float* vid1 = (const float*)d_in[1];
    float* out = (float*)d_out;
    cudaFuncSetAttribute(nls_kernel, cudaFuncAttributeMaxDynamicSharedMemorySize,
                         SMEM_BYTES);
    nls_kernel<<<384, THREADS, SMEM_BYTES>>>(vid0, vid1, out);
}